// round 4
// baseline (speedup 1.0000x reference)
#include <cuda_runtime.h>
#include <cuda_bf16.h>
#include <math.h>

// Problem constants
#define HID    1024
#define BATCH  256
#define NLAYER 3
#define NPROP  4
#define SEQT   128
#define NOUT   47
#define NVOCAB 47
#define NG     4096   // 4*HID

// GEMM tiling (fp32 SIMT)
#define TB 128
#define TG 64
#define KT 32
#define NT 256

// ---------------- device scratch (static, allocation-free) ----------------
__device__ float  g_Wcat[2][NG][2 * HID];   // layers 1,2: [W_ih | W_hh], gate-reordered
__device__ float  g_Whh0[NG][HID];          // layer 0 W_hh, gate-reordered
__device__ float  g_bih[NLAYER][NG];        // b_ih reordered (fp32)
__device__ float  g_bhh[NLAYER][NG];        // b_hh reordered (fp32)
__device__ double g_emb_table[NVOCAB][NG];  // W_ih0[:, :H] @ emb[v], reordered (fp64, no bias)
__device__ double g_base0[BATCH][NG];       // W_ih0[:, H:] @ prop[b], reordered (fp64, no bias)
__device__ float  g_h[NLAYER][2][BATCH][HID]; // double-buffered hidden state
__device__ float  g_c[NLAYER][BATCH][HID];
__device__ int    g_tok[BATCH];

// ---------------- XLA-matched transcendentals ----------------
// XLA GPU f32 tanh: rational polynomial, FMA Horner in x^2,
// clamp to +-7.90531110763549805, passthrough for |x| < 0.0004.
__device__ __forceinline__ float xla_tanh(float x) {
    float ax = fabsf(x);
    float xc = fminf(fmaxf(x, -7.90531110763549805f), 7.90531110763549805f);
    float x2 = xc * xc;
    float np = -2.76076847742355e-16f;
    np = fmaf(x2, np, 2.00018790482477e-13f);
    np = fmaf(x2, np, -8.60467152213735e-11f);
    np = fmaf(x2, np, 5.12229709037114e-08f);
    np = fmaf(x2, np, 1.48572235717979e-05f);
    np = fmaf(x2, np, 6.37261928875436e-04f);
    np = fmaf(x2, np, 4.89352455891786e-03f);
    float num = xc * np;
    float dp = 1.19825839466702e-06f;
    dp = fmaf(x2, dp, 1.18534705686654e-04f);
    dp = fmaf(x2, dp, 2.26843463243900e-03f);
    dp = fmaf(x2, dp, 4.89352518554385e-03f);
    float r = __fdiv_rn(num, dp);
    return (ax < 0.0004f) ? x : r;
}
// XLA logistic_expander: sigmoid(x) = 0.5 + 0.5 * tanh(0.5 * x)
__device__ __forceinline__ float xla_sigmoid(float x) {
    return fmaf(0.5f, xla_tanh(0.5f * x), 0.5f);
}

// ---------------- precompute kernels ----------------

__global__ void prep_state() {
    int n_h = NLAYER * 2 * BATCH * HID;
    int n_c = NLAYER * BATCH * HID;
    float* ph = (float*)g_h;
    float* pc = (float*)g_c;
    for (int i = blockIdx.x * blockDim.x + threadIdx.x; i < n_h + n_c + BATCH;
         i += gridDim.x * blockDim.x) {
        if (i < n_h) ph[i] = 0.f;
        else if (i < n_h + n_c) pc[i - n_h] = 0.f;
        else g_tok[i - n_h - n_c] = 0;  // initial token = 0
    }
}

// Reorder weights: gate-row gr = j*4 + g  <-  original row g*HID + j
__global__ void prep_reorder(const float* __restrict__ Wih_rest,  // [2][NG][HID]
                             const float* __restrict__ Whh,       // [3][NG][HID]
                             const float* __restrict__ bih,       // [3][NG]
                             const float* __restrict__ bhh) {     // [3][NG]
    const int N1 = 2 * NG * 2 * HID;   // g_Wcat
    const int N2 = NG * HID;           // g_Whh0
    const int N3 = NLAYER * NG;        // biases
    for (int i = blockIdx.x * blockDim.x + threadIdx.x; i < N1 + N2 + N3;
         i += gridDim.x * blockDim.x) {
        if (i < N1) {
            int lm = i / (NG * 2 * HID);
            int r  = (i / (2 * HID)) % NG;
            int k  = i % (2 * HID);
            int row = (r & 3) * HID + (r >> 2);
            float v = (k < HID) ? Wih_rest[((size_t)lm * NG + row) * HID + k]
                                : Whh[((size_t)(lm + 1) * NG + row) * HID + (k - HID)];
            g_Wcat[lm][r][k] = v;
        } else if (i < N1 + N2) {
            int j2 = i - N1;
            int r = j2 / HID, k = j2 % HID;
            int row = (r & 3) * HID + (r >> 2);
            g_Whh0[r][k] = Whh[(size_t)row * HID + k];  // W_hh[0]
        } else {
            int j2 = i - N1 - N2;
            int l = j2 / NG, r = j2 % NG;
            int row = (r & 3) * HID + (r >> 2);
            g_bih[l][r] = bih[l * NG + row];
            g_bhh[l][r] = bhh[l * NG + row];
        }
    }
}

// gate_emb[v][gr] = sum_k emb[v][k] * W_ih0[row][k]  (fp64 exact, no bias)
__global__ void prep_emb_table(const float* __restrict__ emb,    // [47][HID]
                               const float* __restrict__ Wih0) { // [NG][HID+NPROP]
    int idx = blockIdx.x * blockDim.x + threadIdx.x;
    if (idx >= NVOCAB * NG) return;
    int v = idx / NG, r = idx % NG;
    int row = (r & 3) * HID + (r >> 2);
    const float* e = emb + (size_t)v * HID;
    const float* w = Wih0 + (size_t)row * (HID + NPROP);
    double s = 0.0;
    for (int q = 0; q < HID; q++) s += (double)e[q] * (double)w[q];
    g_emb_table[v][r] = s;
}

// base0[b][gr] = sum_p prop[b][p] * W_ih0[row][HID+p]   (fp64, no bias)
__global__ void prep_base0(const float* __restrict__ prop,   // [BATCH][NPROP]
                           const float* __restrict__ Wih0) {
    int idx = blockIdx.x * blockDim.x + threadIdx.x;
    if (idx >= BATCH * NG) return;
    int b = idx / NG, r = idx % NG;
    int row = (r & 3) * HID + (r >> 2);
    double s = 0.0;
    const float* wr = Wih0 + (size_t)row * (HID + NPROP) + HID;
    for (int p = 0; p < NPROP; p++) s += (double)prop[b * NPROP + p] * (double)wr[p];
    g_base0[b][r] = s;
}

// ---------------- main per-step fused LSTM-layer GEMM (fp32 SIMT) ----------------
// XLA rounding points: ih-GEMM and hh-GEMM rounded to f32 separately, then
// gates = ((ih + hh) + b_ih) + b_hh in f32, then XLA-matched activations.
template <bool L0>
__global__ __launch_bounds__(NT)
void lstm_layer_kernel(int layer, int par) {
    __shared__ float sA[KT][TB + 4];
    __shared__ float sW[KT][TG + 4];

    int tid = threadIdx.x;
    int gl = tid & 15;      // 16 lanes * 4 gate cols = 64
    int bl = tid >> 4;      // 16 lanes * 8 batch rows = 128
    int gr_base = blockIdx.x * TG;
    int b_base  = blockIdx.y * TB;

    // ih half input (layers 1,2): new h from layer below; hh half: own old h.
    const float* Xih = L0 ? nullptr : &g_h[layer - 1][par ^ 1][0][0];
    const float* Xhh = L0 ? &g_h[0][par][0][0] : &g_h[layer][par][0][0];
    const float* W   = L0 ? &g_Whh0[gr_base][0] : &g_Wcat[layer - 1][gr_base][0];
    const int WROW   = L0 ? HID : 2 * HID;

    float acc[8][4];
    float r_ih[8][4];
#pragma unroll
    for (int i = 0; i < 8; i++)
#pragma unroll
        for (int j = 0; j < 4; j++) acc[i][j] = 0.f;

    const int nhalf = L0 ? 1 : 2;
    for (int half = 0; half < nhalf; half++) {
        const float* X = (!L0 && half == 0) ? Xih : Xhh;
        const int koff = (L0 ? 0 : half * HID);

        for (int kt0 = 0; kt0 < HID; kt0 += KT) {
            __syncthreads();
            // A tile [KT][TB] transposed from X[b][k]; 4 float4 per thread
#pragma unroll
            for (int i = 0; i < 4; i++) {
                int idx4 = tid + i * NT;       // 0..1023
                int b  = idx4 >> 3;            // 0..127
                int kq = idx4 & 7;             // 0..7
                float4 v = *(const float4*)(X + (size_t)(b_base + b) * HID + kt0 + kq * 4);
                sA[kq * 4 + 0][b] = v.x;
                sA[kq * 4 + 1][b] = v.y;
                sA[kq * 4 + 2][b] = v.z;
                sA[kq * 4 + 3][b] = v.w;
            }
            // W tile [KT][TG]; 2 float4 per thread
#pragma unroll
            for (int i = 0; i < 2; i++) {
                int idx4 = tid + i * NT;       // 0..511
                int gr = idx4 >> 3;            // 0..63
                int kq = idx4 & 7;
                float4 v = *(const float4*)(W + (size_t)gr * WROW + koff + kt0 + kq * 4);
                sW[kq * 4 + 0][gr] = v.x;
                sW[kq * 4 + 1][gr] = v.y;
                sW[kq * 4 + 2][gr] = v.z;
                sW[kq * 4 + 3][gr] = v.w;
            }
            __syncthreads();
#pragma unroll
            for (int k = 0; k < KT; k++) {
                float4 a0 = *(float4*)&sA[k][bl * 8];
                float4 a1 = *(float4*)&sA[k][bl * 8 + 4];
                float4 w4 = *(float4*)&sW[k][gl * 4];
                float av[8] = {a0.x, a0.y, a0.z, a0.w, a1.x, a1.y, a1.z, a1.w};
                float wv[4] = {w4.x, w4.y, w4.z, w4.w};
#pragma unroll
                for (int ib = 0; ib < 8; ib++)
#pragma unroll
                    for (int ig = 0; ig < 4; ig++)
                        acc[ib][ig] = fmaf(av[ib], wv[ig], acc[ib][ig]);
            }
        }
        if (!L0 && half == 0) {
            // snapshot ih-GEMM output (XLA rounds each GEMM result to f32)
#pragma unroll
            for (int ib = 0; ib < 8; ib++)
#pragma unroll
                for (int ig = 0; ig < 4; ig++) {
                    r_ih[ib][ig] = acc[ib][ig];
                    acc[ib][ig] = 0.f;
                }
        }
    }

    // Fused LSTM epilogue: thread holds the 4 gates (i,f,g,o) of unit j for 8 rows
    int gr0 = gr_base + gl * 4;
    int j   = gr0 >> 2;
    float* Hout = &g_h[layer][par ^ 1][0][0];
    float* C    = &g_c[layer][0][0];
    const float* bi = &g_bih[layer][gr0];
    const float* bh = &g_bhh[layer][gr0];
#pragma unroll
    for (int ib = 0; ib < 8; ib++) {
        int b = b_base + bl * 8 + ib;
        float p[4];
        if (L0) {
            int tk = g_tok[b];
#pragma unroll
            for (int gg = 0; gg < 4; gg++) {
                float vih = (float)(g_emb_table[tk][gr0 + gg] + g_base0[b][gr0 + gg]);
                float vhh = acc[ib][gg];
                p[gg] = ((vih + vhh) + bi[gg]) + bh[gg];
            }
        } else {
#pragma unroll
            for (int gg = 0; gg < 4; gg++) {
                p[gg] = ((r_ih[ib][gg] + acc[ib][gg]) + bi[gg]) + bh[gg];
            }
        }
        float iv = xla_sigmoid(p[0]);
        float fv = xla_sigmoid(p[1]);
        float gv = xla_tanh(p[2]);
        float ov = xla_sigmoid(p[3]);
        float c = C[(size_t)b * HID + j];
        c = fmaf(fv, c, iv * gv);           // sigmoid(f)*c + sigmoid(i)*tanh(g)
        C[(size_t)b * HID + j] = c;
        Hout[(size_t)b * HID + j] = ov * xla_tanh(c);
    }
}

// ---------------- decode: logits (fp64 exact, rounded once), argmax ----------------
__global__ void decode_kernel(const float* __restrict__ Wdec,  // [47][HID]
                              const float* __restrict__ bdec,  // [47]
                              float* __restrict__ out, int t, int par) {
    __shared__ float slog[NOUT];
    int b = blockIdx.x;
    int tid = threadIdx.x;
    int w = tid >> 5, lane = tid & 31;
    const float* h2 = &g_h[2][par ^ 1][b][0];
    for (int o = w; o < NOUT; o += 8) {
        const float* wr = Wdec + (size_t)o * HID;
        double s = 0.0;
        for (int k = lane; k < HID; k += 32) s += (double)h2[k] * (double)wr[k];
#pragma unroll
        for (int off = 16; off; off >>= 1) s += __shfl_down_sync(0xffffffffu, s, off);
        if (lane == 0) {
            float sf = (float)s;          // GEMM output rounded to f32
            sf = sf + bdec[o];            // then + b_dec (f32)
            slog[o] = sf;
            out[((size_t)b * SEQT + t) * NOUT + o] = sf;
        }
    }
    __syncthreads();
    if (tid == 0) {
        int best = 0;
        float bv = slog[0];
        for (int o = 1; o < NOUT; o++)
            if (slog[o] > bv) { bv = slog[o]; best = o; }  // first-max tie rule (jnp.argmax)
        g_tok[b] = best;
    }
}

// ---------------- finalize: copy final h, c into output tail ----------------
__global__ void finalize_kernel(float* __restrict__ out) {
    const int HB = NLAYER * BATCH * HID;  // 786432
    const size_t base = (size_t)BATCH * SEQT * NOUT;
    for (int i = blockIdx.x * blockDim.x + threadIdx.x; i < 2 * HB;
         i += gridDim.x * blockDim.x) {
        if (i < HB) {
            int l = i / (BATCH * HID);
            int r = i % (BATCH * HID);
            // final h in parity-0 buffer (last write at t=127 -> (127+1)&1 = 0)
            out[base + i] = ((float*)g_h)[((size_t)l * 2 + 0) * BATCH * HID + r];
        } else {
            out[base + i] = ((float*)g_c)[i - HB];
        }
    }
}

// ---------------- launcher ----------------
extern "C" void kernel_launch(void* const* d_in, const int* in_sizes, int n_in,
                              void* d_out, int out_size) {
    (void)in_sizes; (void)n_in; (void)out_size;
    // Input order: x, properties, emb, W_dec, b_dec, W_ih0, W_ih_rest, W_hh, b_ih, b_hh
    const float* properties = (const float*)d_in[1];
    const float* emb        = (const float*)d_in[2];
    const float* W_dec      = (const float*)d_in[3];
    const float* b_dec      = (const float*)d_in[4];
    const float* W_ih0      = (const float*)d_in[5];
    const float* W_ih_rest  = (const float*)d_in[6];
    const float* W_hh       = (const float*)d_in[7];
    const float* b_ih       = (const float*)d_in[8];
    const float* b_hh       = (const float*)d_in[9];
    float* out = (float*)d_out;

    prep_state<<<512, 256>>>();
    prep_reorder<<<8192, 256>>>(W_ih_rest, W_hh, b_ih, b_hh);
    prep_emb_table<<<(NVOCAB * NG + 255) / 256, 256>>>(emb, W_ih0);
    prep_base0<<<(BATCH * NG + 255) / 256, 256>>>(properties, W_ih0);

    dim3 grid(NG / TG, BATCH / TB);  // 64 x 2 = 128 blocks
    for (int t = 0; t < SEQT; t++) {
        int par = t & 1;
        lstm_layer_kernel<true><<<grid, NT>>>(0, par);
        lstm_layer_kernel<false><<<grid, NT>>>(1, par);
        lstm_layer_kernel<false><<<grid, NT>>>(2, par);
        decode_kernel<<<BATCH, 256>>>(W_dec, b_dec, out, t, par);
    }
    finalize_kernel<<<1536, 256>>>(out);
}

// round 6
// speedup vs baseline: 1.7422x; 1.7422x over previous
#include <cuda_runtime.h>
#include <cuda_fp16.h>
#include <math.h>

// Problem constants
#define HID    1024
#define BATCH  256
#define NLAYER 3
#define NPROP  4
#define SEQT   128
#define NOUT   47
#define NVOCAB 47
#define NG     4096   // 4*HID

#define INV2048 4.8828125e-4f

// ---------------- device scratch (static, allocation-free) ----------------
// Weights in mma-fragment layout, fp16 split-2 (hi, lo*2048), gate-reordered gr=4j+g.
// wf12[lm][mt][ktg][lane][0..3]=hi regs, [4..7]=lo regs  (K=2048: ih half kt 0..63, hh half 64..127)
__device__ unsigned g_wf12[2][256][128][32][8];   // 67.1 MB
__device__ unsigned g_wf0 [256][64][32][8];       // 16.8 MB (layer0 hh, K=1024)
__device__ float  g_bih[NLAYER][NG];
__device__ float  g_bhh[NLAYER][NG];
__device__ double g_emb_table[NVOCAB][NG];        // W_ih0[:, :H] @ emb[v]  (exact)
__device__ double g_base0[BATCH][NG];             // W_ih0[:, H:] @ prop[b] (exact)
__device__ float  g_h[NLAYER][2][BATCH][HID];     // double-buffered hidden (fp32)
__device__ __half g_xhi[NLAYER][2][BATCH][HID];   // fp16 split hi of h
__device__ __half g_xlo[NLAYER][2][BATCH][HID];   // fp16 split lo (*2048) of h
__device__ float  g_c[NLAYER][BATCH][HID];
__device__ int    g_tok[BATCH];

// ---------------- XLA-matched transcendentals ----------------
__device__ __forceinline__ float xla_tanh(float x) {
    float ax = fabsf(x);
    float xc = fminf(fmaxf(x, -7.90531110763549805f), 7.90531110763549805f);
    float x2 = xc * xc;
    float np = -2.76076847742355e-16f;
    np = fmaf(x2, np, 2.00018790482477e-13f);
    np = fmaf(x2, np, -8.60467152213735e-11f);
    np = fmaf(x2, np, 5.12229709037114e-08f);
    np = fmaf(x2, np, 1.48572235717979e-05f);
    np = fmaf(x2, np, 6.37261928875436e-04f);
    np = fmaf(x2, np, 4.89352455891786e-03f);
    float num = xc * np;
    float dp = 1.19825839466702e-06f;
    dp = fmaf(x2, dp, 1.18534705686654e-04f);
    dp = fmaf(x2, dp, 2.26843463243900e-03f);
    dp = fmaf(x2, dp, 4.89352518554385e-03f);
    float r = __fdiv_rn(num, dp);
    return (ax < 0.0004f) ? x : r;
}
__device__ __forceinline__ float xla_sigmoid(float x) {
    return fmaf(0.5f, xla_tanh(0.5f * x), 0.5f);
}

// ---------------- mma.sync wrapper ----------------
__device__ __forceinline__ void mma16816(float* d, const unsigned* a, const unsigned* b) {
    asm volatile(
        "mma.sync.aligned.m16n8k16.row.col.f32.f16.f16.f32 "
        "{%0,%1,%2,%3}, {%4,%5,%6,%7}, {%8,%9}, {%0,%1,%2,%3};\n"
        : "+f"(d[0]), "+f"(d[1]), "+f"(d[2]), "+f"(d[3])
        : "r"(a[0]), "r"(a[1]), "r"(a[2]), "r"(a[3]), "r"(b[0]), "r"(b[1]));
}

__device__ __forceinline__ unsigned pack_split(float v0, float v1, unsigned& lo_out) {
    __half h0 = __float2half_rn(v0);
    __half h1 = __float2half_rn(v1);
    __half l0 = __float2half_rn((v0 - __half2float(h0)) * 2048.f);
    __half l1 = __float2half_rn((v1 - __half2float(h1)) * 2048.f);
    __half2 hp = __halves2half2(h0, h1);
    __half2 lp = __halves2half2(l0, l1);
    lo_out = *(unsigned*)&lp;
    return *(unsigned*)&hp;
}

// ---------------- precompute kernels ----------------

__global__ void prep_state() {
    const int NH = NLAYER * 2 * BATCH * HID;        // fp32 h
    const int NC = NLAYER * BATCH * HID;            // fp32 c
    const int NX = NLAYER * 2 * BATCH * HID / 2;    // u32 words of xhi (and xlo)
    float* ph = (float*)g_h;
    float* pc = (float*)g_c;
    unsigned* phi = (unsigned*)g_xhi;
    unsigned* plo = (unsigned*)g_xlo;
    int total = NH + NC + 2 * NX + BATCH;
    for (int i = blockIdx.x * blockDim.x + threadIdx.x; i < total;
         i += gridDim.x * blockDim.x) {
        if (i < NH) ph[i] = 0.f;
        else if (i < NH + NC) pc[i - NH] = 0.f;
        else if (i < NH + NC + NX) phi[i - NH - NC] = 0u;
        else if (i < NH + NC + 2 * NX) plo[i - NH - NC - NX] = 0u;
        else g_tok[i - NH - NC - 2 * NX] = 0;
    }
}

__global__ void prep_bias(const float* __restrict__ bih, const float* __restrict__ bhh) {
    int i = blockIdx.x * blockDim.x + threadIdx.x;
    if (i >= NLAYER * NG) return;
    int l = i / NG, r = i % NG;
    int row = (r & 3) * HID + (r >> 2);
    g_bih[l][r] = bih[l * NG + row];
    g_bhh[l][r] = bhh[l * NG + row];
}

// weights layers 1,2: [W_ih | W_hh] fragments
__global__ void prep_wf12(const float* __restrict__ Wih_rest,  // [2][NG][HID]
                          const float* __restrict__ Whh) {     // [3][NG][HID]
    int idx = blockIdx.x * blockDim.x + threadIdx.x;
    if (idx >= 2 * 256 * 128 * 32 * 4) return;
    int r  = idx & 3;
    int T  = (idx >> 2) & 31;
    int kt = (idx >> 7) & 127;
    int mt = (idx >> 14) & 255;
    int lm = idx >> 22;
    int gr = mt * 16 + (T >> 2) + 8 * (r & 1);
    int k  = kt * 16 + 2 * (T & 3) + 8 * (r >> 1);
    int row = (gr & 3) * HID + (gr >> 2);
    float v0, v1;
    if (k < HID) {
        const float* s = Wih_rest + ((size_t)lm * NG + row) * HID + k;
        v0 = s[0]; v1 = s[1];
    } else {
        const float* s = Whh + ((size_t)(lm + 1) * NG + row) * HID + (k - HID);
        v0 = s[0]; v1 = s[1];
    }
    unsigned lo, hi = pack_split(v0, v1, lo);
    g_wf12[lm][mt][kt][T][r] = hi;
    g_wf12[lm][mt][kt][T][4 + r] = lo;
}

// weights layer 0 (W_hh[0]) fragments
__global__ void prep_wf0(const float* __restrict__ Whh) {
    int idx = blockIdx.x * blockDim.x + threadIdx.x;
    if (idx >= 256 * 64 * 32 * 4) return;
    int r  = idx & 3;
    int T  = (idx >> 2) & 31;
    int kt = (idx >> 7) & 63;
    int mt = idx >> 13;
    int gr = mt * 16 + (T >> 2) + 8 * (r & 1);
    int k  = kt * 16 + 2 * (T & 3) + 8 * (r >> 1);
    int row = (gr & 3) * HID + (gr >> 2);
    const float* s = Whh + (size_t)row * HID + k;
    unsigned lo, hi = pack_split(s[0], s[1], lo);
    g_wf0[mt][kt][T][r] = hi;
    g_wf0[mt][kt][T][4 + r] = lo;
}

// emb_table: exact fp32 dot via FMA two-product + two-sum (fp64-grade, fp32 speed)
__global__ void prep_emb_table(const float* __restrict__ emb,    // [47][HID]
                               const float* __restrict__ Wih0) { // [NG][HID+NPROP]
    int idx = blockIdx.x * blockDim.x + threadIdx.x;
    if (idx >= NVOCAB * NG) return;
    int v = idx / NG, r = idx % NG;
    int row = (r & 3) * HID + (r >> 2);
    const float* e = emb + (size_t)v * HID;
    const float* w = Wih0 + (size_t)row * (HID + NPROP);
    float s = 0.f, comp = 0.f;
    for (int q = 0; q < HID; q++) {
        float a = e[q], b = w[q];
        float p = a * b;
        float ep = fmaf(a, b, -p);          // exact product residual
        float t = s + p;                     // two-sum
        float z = t - s;
        float err = (s - (t - z)) + (p - z);
        s = t;
        comp += ep + err;
    }
    g_emb_table[v][r] = (double)s + (double)comp;
}

// base0: fp64 (P=4, trivial)
__global__ void prep_base0(const float* __restrict__ prop,
                           const float* __restrict__ Wih0) {
    int idx = blockIdx.x * blockDim.x + threadIdx.x;
    if (idx >= BATCH * NG) return;
    int b = idx / NG, r = idx % NG;
    int row = (r & 3) * HID + (r >> 2);
    double s = 0.0;
    const float* wr = Wih0 + (size_t)row * (HID + NPROP) + HID;
    for (int p = 0; p < NPROP; p++) s += (double)prop[b * NPROP + p] * (double)wr[p];
    g_base0[b][r] = s;
}

// ---------------- fused LSTM layer: fp16-split mma GEMM + epilogue ----------------
// CTA tile: 128 gr x 64 b. 8 warps = (4 gr-warps) x (2 b-warps), warp tile 32x32.
// gates staged via smem to regroup the 4 gates of each unit for the LSTM update.
template <bool L0>
__global__ __launch_bounds__(256, 1)
void lstm_mma_kernel(int layer, int par) {
    __shared__ float sp[128][66];

    const int tid = threadIdx.x;
    const int wid = tid >> 5;
    const int T   = tid & 31;
    const int mw  = wid & 3;
    const int nw  = wid >> 2;
    const int grbase = blockIdx.x * 128;
    const int bbase  = blockIdx.y * 64;
    const int tq = T >> 2;   // 0..7
    const int tr = T & 3;    // 0..3

    float accA[2][4][4], accB[2][4][4], rih[2][4][4];
#pragma unroll
    for (int mi = 0; mi < 2; mi++)
#pragma unroll
        for (int ni = 0; ni < 4; ni++)
#pragma unroll
            for (int q = 0; q < 4; q++) { accA[mi][ni][q] = 0.f; accB[mi][ni][q] = 0.f; }

    const int nhalf = L0 ? 1 : 2;
    for (int half = 0; half < nhalf; half++) {
        const __half* Xhi;
        const __half* Xlo;
        if (L0)            { Xhi = &g_xhi[0][par][0][0];           Xlo = &g_xlo[0][par][0][0]; }
        else if (half == 0){ Xhi = &g_xhi[layer-1][par^1][0][0];   Xlo = &g_xlo[layer-1][par^1][0][0]; }
        else               { Xhi = &g_xhi[layer][par][0][0];       Xlo = &g_xlo[layer][par][0][0]; }

        for (int kt = 0; kt < 64; kt++) {
            unsigned ahi[2][4], alo[2][4];
#pragma unroll
            for (int mi = 0; mi < 2; mi++) {
                int mt = blockIdx.x * 8 + mw * 2 + mi;
                const uint4* wf = L0 ? (const uint4*)&g_wf0[mt][kt][T][0]
                                     : (const uint4*)&g_wf12[layer-1][mt][half*64 + kt][T][0];
                uint4 h4 = wf[0];
                uint4 l4 = wf[1];
                ahi[mi][0] = h4.x; ahi[mi][1] = h4.y; ahi[mi][2] = h4.z; ahi[mi][3] = h4.w;
                alo[mi][0] = l4.x; alo[mi][1] = l4.y; alo[mi][2] = l4.z; alo[mi][3] = l4.w;
            }
            unsigned bhi[4][2], blo[4][2];
            const int k0 = kt * 16 + 2 * tr;
#pragma unroll
            for (int ni = 0; ni < 4; ni++) {
                int n = bbase + nw * 32 + ni * 8 + tq;
                const __half* ph = Xhi + (size_t)n * HID + k0;
                const __half* pl = Xlo + (size_t)n * HID + k0;
                bhi[ni][0] = *(const unsigned*)ph;
                bhi[ni][1] = *(const unsigned*)(ph + 8);
                blo[ni][0] = *(const unsigned*)pl;
                blo[ni][1] = *(const unsigned*)(pl + 8);
            }
#pragma unroll
            for (int mi = 0; mi < 2; mi++)
#pragma unroll
                for (int ni = 0; ni < 4; ni++) {
                    mma16816(accA[mi][ni], ahi[mi], bhi[ni]);   // hi*hi
                    mma16816(accB[mi][ni], ahi[mi], blo[ni]);   // hi*lo
                    mma16816(accB[mi][ni], alo[mi], bhi[ni]);   // lo*hi
                }
        }
        if (!L0 && half == 0) {
#pragma unroll
            for (int mi = 0; mi < 2; mi++)
#pragma unroll
                for (int ni = 0; ni < 4; ni++)
#pragma unroll
                    for (int q = 0; q < 4; q++) {
                        rih[mi][ni][q] = fmaf(accB[mi][ni][q], INV2048, accA[mi][ni][q]);
                        accA[mi][ni][q] = 0.f;
                        accB[mi][ni][q] = 0.f;
                    }
        }
    }

    // combine, add biases (layers 1,2), stage gates to smem
#pragma unroll
    for (int mi = 0; mi < 2; mi++) {
        int r0 = mw * 32 + mi * 16 + tq;          // local gr row 0..127
        float bi0 = 0.f, bh0 = 0.f, bi8 = 0.f, bh8 = 0.f;
        if (!L0) {
            bi0 = g_bih[layer][grbase + r0];      bh0 = g_bhh[layer][grbase + r0];
            bi8 = g_bih[layer][grbase + r0 + 8];  bh8 = g_bhh[layer][grbase + r0 + 8];
        }
#pragma unroll
        for (int ni = 0; ni < 4; ni++) {
            int c0 = nw * 32 + ni * 8 + 2 * tr;
            float d0 = fmaf(accB[mi][ni][0], INV2048, accA[mi][ni][0]);
            float d1 = fmaf(accB[mi][ni][1], INV2048, accA[mi][ni][1]);
            float d2 = fmaf(accB[mi][ni][2], INV2048, accA[mi][ni][2]);
            float d3 = fmaf(accB[mi][ni][3], INV2048, accA[mi][ni][3]);
            if (!L0) {
                d0 = ((rih[mi][ni][0] + d0) + bi0) + bh0;
                d1 = ((rih[mi][ni][1] + d1) + bi0) + bh0;
                d2 = ((rih[mi][ni][2] + d2) + bi8) + bh8;
                d3 = ((rih[mi][ni][3] + d3) + bi8) + bh8;
            }
            *(float2*)&sp[r0][c0]     = make_float2(d0, d1);
            *(float2*)&sp[r0 + 8][c0] = make_float2(d2, d3);
        }
    }
    __syncthreads();

    // LSTM epilogue: regroup 4 gates per unit; 32 units x 64 b per CTA
    const int un = tid & 31;
    const int bq = tid >> 5;
    const int j  = (grbase >> 2) + un;
    float* C    = &g_c[layer][0][0];
    float* Hout = &g_h[layer][par ^ 1][0][0];
    __half* XhiO = &g_xhi[layer][par ^ 1][0][0];
    __half* XloO = &g_xlo[layer][par ^ 1][0][0];
    const int gr0 = grbase + un * 4;
#pragma unroll
    for (int r = 0; r < 8; r++) {
        int bl = bq * 8 + r;
        int b  = bbase + bl;
        float p0 = sp[un * 4 + 0][bl];
        float p1 = sp[un * 4 + 1][bl];
        float p2 = sp[un * 4 + 2][bl];
        float p3 = sp[un * 4 + 3][bl];
        if (L0) {
            int tk = g_tok[b];
            float v0 = (float)(g_emb_table[tk][gr0 + 0] + g_base0[b][gr0 + 0]);
            float v1 = (float)(g_emb_table[tk][gr0 + 1] + g_base0[b][gr0 + 1]);
            float v2 = (float)(g_emb_table[tk][gr0 + 2] + g_base0[b][gr0 + 2]);
            float v3 = (float)(g_emb_table[tk][gr0 + 3] + g_base0[b][gr0 + 3]);
            p0 = ((v0 + p0) + g_bih[0][gr0 + 0]) + g_bhh[0][gr0 + 0];
            p1 = ((v1 + p1) + g_bih[0][gr0 + 1]) + g_bhh[0][gr0 + 1];
            p2 = ((v2 + p2) + g_bih[0][gr0 + 2]) + g_bhh[0][gr0 + 2];
            p3 = ((v3 + p3) + g_bih[0][gr0 + 3]) + g_bhh[0][gr0 + 3];
        }
        float iv = xla_sigmoid(p0);
        float fv = xla_sigmoid(p1);
        float gv = xla_tanh(p2);
        float ov = xla_sigmoid(p3);
        float c = C[(size_t)b * HID + j];
        c = fmaf(fv, c, iv * gv);
        C[(size_t)b * HID + j] = c;
        float h = ov * xla_tanh(c);
        Hout[(size_t)b * HID + j] = h;
        __half hh = __float2half_rn(h);
        XhiO[(size_t)b * HID + j] = hh;
        XloO[(size_t)b * HID + j] = __float2half_rn((h - __half2float(hh)) * 2048.f);
    }
}

// ---------------- decode: fp32 logits, output write, greedy argmax ----------------
__global__ void decode_kernel(const float* __restrict__ Wdec,
                              const float* __restrict__ bdec,
                              float* __restrict__ out, int t, int par) {
    __shared__ float slog[NOUT];
    int b = blockIdx.x;
    int tid = threadIdx.x;
    int w = tid >> 5, lane = tid & 31;
    const float* h2 = &g_h[2][par ^ 1][b][0];
    for (int o = w; o < NOUT; o += 8) {
        const float* wr = Wdec + (size_t)o * HID;
        float s = 0.f;
        for (int k = lane; k < HID; k += 32) s = fmaf(h2[k], wr[k], s);
#pragma unroll
        for (int off = 16; off; off >>= 1) s += __shfl_down_sync(0xffffffffu, s, off);
        if (lane == 0) {
            float sf = s + bdec[o];
            slog[o] = sf;
            out[((size_t)b * SEQT + t) * NOUT + o] = sf;
        }
    }
    __syncthreads();
    if (tid == 0) {
        int best = 0;
        float bv = slog[0];
        for (int o = 1; o < NOUT; o++)
            if (slog[o] > bv) { bv = slog[o]; best = o; }  // first-max tie rule
        g_tok[b] = best;
    }
}

// ---------------- finalize ----------------
__global__ void finalize_kernel(float* __restrict__ out) {
    const int HB = NLAYER * BATCH * HID;
    const size_t base = (size_t)BATCH * SEQT * NOUT;
    for (int i = blockIdx.x * blockDim.x + threadIdx.x; i < 2 * HB;
         i += gridDim.x * blockDim.x) {
        if (i < HB) {
            int l = i / (BATCH * HID);
            int r = i % (BATCH * HID);
            out[base + i] = ((float*)g_h)[((size_t)l * 2 + 0) * BATCH * HID + r];
        } else {
            out[base + i] = ((float*)g_c)[i - HB];
        }
    }
}

// ---------------- launcher ----------------
extern "C" void kernel_launch(void* const* d_in, const int* in_sizes, int n_in,
                              void* d_out, int out_size) {
    (void)in_sizes; (void)n_in; (void)out_size;
    // Inputs: x, properties, emb, W_dec, b_dec, W_ih0, W_ih_rest, W_hh, b_ih, b_hh
    const float* properties = (const float*)d_in[1];
    const float* emb        = (const float*)d_in[2];
    const float* W_dec      = (const float*)d_in[3];
    const float* b_dec      = (const float*)d_in[4];
    const float* W_ih0      = (const float*)d_in[5];
    const float* W_ih_rest  = (const float*)d_in[6];
    const float* W_hh       = (const float*)d_in[7];
    const float* b_ih       = (const float*)d_in[8];
    const float* b_hh       = (const float*)d_in[9];
    float* out = (float*)d_out;

    prep_state<<<1024, 256>>>();
    prep_bias<<<(NLAYER * NG + 255) / 256, 256>>>(b_ih, b_hh);
    prep_wf12<<<(2 * 256 * 128 * 32 * 4 + 255) / 256, 256>>>(W_ih_rest, W_hh);
    prep_wf0<<<(256 * 64 * 32 * 4 + 255) / 256, 256>>>(W_hh);
    prep_emb_table<<<(NVOCAB * NG + 255) / 256, 256>>>(emb, W_ih0);
    prep_base0<<<(BATCH * NG + 255) / 256, 256>>>(properties, W_ih0);

    dim3 grid(NG / 128, BATCH / 64);   // 32 x 4 = 128 CTAs
    for (int t = 0; t < SEQT; t++) {
        int par = t & 1;
        lstm_mma_kernel<true><<<grid, 256>>>(0, par);
        lstm_mma_kernel<false><<<grid, 256>>>(1, par);
        lstm_mma_kernel<false><<<grid, 256>>>(2, par);
        decode_kernel<<<BATCH, 256>>>(W_dec, b_dec, out, t, par);
    }
    finalize_kernel<<<1536, 256>>>(out);
}

// round 7
// speedup vs baseline: 1.9454x; 1.1167x over previous
#include <cuda_runtime.h>
#include <cuda_bf16.h>
#include <math.h>

// Problem constants
#define HID    1024
#define BATCH  256
#define NLAYER 3
#define NPROP  4
#define SEQT   128
#define NOUT   47
#define NVOCAB 47
#define NG     4096   // 4*HID

// ---------------- device scratch (static, allocation-free) ----------------
// Weight fragments, bf16 exact split-3 (hi, mid, lo), mma m16n8k16 A-layout,
// gate-reordered gr = 4j+g. Per [mt][kt]: 3 split planes x 32 lanes x uint4.
__device__ unsigned g_w12[2][256][128][3][32][4];  // layers 1,2 [Wih|Whh]: 100.7 MB
__device__ unsigned g_w0 [256][64][3][32][4];      // layer 0 Whh: 25.2 MB
__device__ float  g_bih[NLAYER][NG];
__device__ float  g_bhh[NLAYER][NG];
__device__ double g_emb_table[NVOCAB][NG];         // W_ih0[:,:H] @ emb[v] (exact)
__device__ double g_base0[BATCH][NG];              // W_ih0[:,H:] @ prop[b] (exact)
__device__ float  g_h[NLAYER][2][BATCH][HID];      // double-buffered hidden (fp32)
__device__ __nv_bfloat16 g_xs[3][NLAYER][2][BATCH][HID];  // bf16 split planes of h
__device__ float  g_c[NLAYER][BATCH][HID];
__device__ int    g_tok[BATCH];

// ---------------- XLA-matched transcendentals ----------------
__device__ __forceinline__ float xla_tanh(float x) {
    float ax = fabsf(x);
    float xc = fminf(fmaxf(x, -7.90531110763549805f), 7.90531110763549805f);
    float x2 = xc * xc;
    float np = -2.76076847742355e-16f;
    np = fmaf(x2, np, 2.00018790482477e-13f);
    np = fmaf(x2, np, -8.60467152213735e-11f);
    np = fmaf(x2, np, 5.12229709037114e-08f);
    np = fmaf(x2, np, 1.48572235717979e-05f);
    np = fmaf(x2, np, 6.37261928875436e-04f);
    np = fmaf(x2, np, 4.89352455891786e-03f);
    float num = xc * np;
    float dp = 1.19825839466702e-06f;
    dp = fmaf(x2, dp, 1.18534705686654e-04f);
    dp = fmaf(x2, dp, 2.26843463243900e-03f);
    dp = fmaf(x2, dp, 4.89352518554385e-03f);
    float r = __fdiv_rn(num, dp);
    return (ax < 0.0004f) ? x : r;
}
__device__ __forceinline__ float xla_sigmoid(float x) {
    return fmaf(0.5f, xla_tanh(0.5f * x), 0.5f);
}

// ---------------- mma.sync bf16 wrapper ----------------
__device__ __forceinline__ void mma_bf16(float* d, const unsigned* a, const unsigned* b) {
    asm volatile(
        "mma.sync.aligned.m16n8k16.row.col.f32.bf16.bf16.f32 "
        "{%0,%1,%2,%3}, {%4,%5,%6,%7}, {%8,%9}, {%0,%1,%2,%3};\n"
        : "+f"(d[0]), "+f"(d[1]), "+f"(d[2]), "+f"(d[3])
        : "r"(a[0]), "r"(a[1]), "r"(a[2]), "r"(a[3]), "r"(b[0]), "r"(b[1]));
}

// Exact bf16 split-3 of an fp32 pair, packed (low half = first element)
__device__ __forceinline__ void split3_pack(float v0, float v1,
                                            unsigned& ph, unsigned& pm, unsigned& pl) {
    __nv_bfloat16 h0 = __float2bfloat16(v0), h1 = __float2bfloat16(v1);
    float r0 = v0 - __bfloat162float(h0), r1 = v1 - __bfloat162float(h1);
    __nv_bfloat16 m0 = __float2bfloat16(r0), m1 = __float2bfloat16(r1);
    float s0 = r0 - __bfloat162float(m0), s1 = r1 - __bfloat162float(m1);
    __nv_bfloat16 l0 = __float2bfloat16(s0), l1 = __float2bfloat16(s1);
    __nv_bfloat162 H = __halves2bfloat162(h0, h1);
    __nv_bfloat162 M = __halves2bfloat162(m0, m1);
    __nv_bfloat162 L = __halves2bfloat162(l0, l1);
    ph = *(unsigned*)&H; pm = *(unsigned*)&M; pl = *(unsigned*)&L;
}

// ---------------- precompute kernels ----------------

__global__ void prep_state() {
    const int NH = NLAYER * 2 * BATCH * HID;
    const int NC = NLAYER * BATCH * HID;
    const int NXS = 3 * NLAYER * 2 * BATCH * HID / 2;   // g_xs as u32 words
    float* ph = (float*)g_h;
    float* pc = (float*)g_c;
    unsigned* pxs = (unsigned*)g_xs;
    int total = NH + NC + NXS + BATCH;
    for (int i = blockIdx.x * blockDim.x + threadIdx.x; i < total;
         i += gridDim.x * blockDim.x) {
        if (i < NH) ph[i] = 0.f;
        else if (i < NH + NC) pc[i - NH] = 0.f;
        else if (i < NH + NC + NXS) pxs[i - NH - NC] = 0u;
        else g_tok[i - NH - NC - NXS] = 0;
    }
}

__global__ void prep_bias(const float* __restrict__ bih, const float* __restrict__ bhh) {
    int i = blockIdx.x * blockDim.x + threadIdx.x;
    if (i >= NLAYER * NG) return;
    int l = i / NG, r = i % NG;
    int row = (r & 3) * HID + (r >> 2);
    g_bih[l][r] = bih[l * NG + row];
    g_bhh[l][r] = bhh[l * NG + row];
}

// weights layers 1,2: [W_ih | W_hh] -> bf16x3 fragment planes
__global__ void prep_w12(const float* __restrict__ Wih_rest,  // [2][NG][HID]
                         const float* __restrict__ Whh) {     // [3][NG][HID]
    int idx = blockIdx.x * blockDim.x + threadIdx.x;
    if (idx >= 2 * 256 * 128 * 32 * 4) return;
    int r  = idx & 3;
    int T  = (idx >> 2) & 31;
    int kt = (idx >> 7) & 127;
    int mt = (idx >> 14) & 255;
    int lm = idx >> 22;
    int gr = mt * 16 + (T >> 2) + 8 * (r & 1);
    int k  = kt * 16 + 2 * (T & 3) + 8 * (r >> 1);
    int row = (gr & 3) * HID + (gr >> 2);
    float v0, v1;
    if (k < HID) {
        const float* s = Wih_rest + ((size_t)lm * NG + row) * HID + k;
        v0 = s[0]; v1 = s[1];
    } else {
        const float* s = Whh + ((size_t)(lm + 1) * NG + row) * HID + (k - HID);
        v0 = s[0]; v1 = s[1];
    }
    unsigned ph, pm, pl;
    split3_pack(v0, v1, ph, pm, pl);
    g_w12[lm][mt][kt][0][T][r] = ph;
    g_w12[lm][mt][kt][1][T][r] = pm;
    g_w12[lm][mt][kt][2][T][r] = pl;
}

// layer 0 W_hh fragments
__global__ void prep_w0(const float* __restrict__ Whh) {
    int idx = blockIdx.x * blockDim.x + threadIdx.x;
    if (idx >= 256 * 64 * 32 * 4) return;
    int r  = idx & 3;
    int T  = (idx >> 2) & 31;
    int kt = (idx >> 7) & 63;
    int mt = idx >> 13;
    int gr = mt * 16 + (T >> 2) + 8 * (r & 1);
    int k  = kt * 16 + 2 * (T & 3) + 8 * (r >> 1);
    int row = (gr & 3) * HID + (gr >> 2);
    const float* s = Whh + (size_t)row * HID + k;
    unsigned ph, pm, pl;
    split3_pack(s[0], s[1], ph, pm, pl);
    g_w0[mt][kt][0][T][r] = ph;
    g_w0[mt][kt][1][T][r] = pm;
    g_w0[mt][kt][2][T][r] = pl;
}

// emb_table: exact fp32 dot via FMA two-product + two-sum
__global__ void prep_emb_table(const float* __restrict__ emb,
                               const float* __restrict__ Wih0) {
    int idx = blockIdx.x * blockDim.x + threadIdx.x;
    if (idx >= NVOCAB * NG) return;
    int v = idx / NG, r = idx % NG;
    int row = (r & 3) * HID + (r >> 2);
    const float* e = emb + (size_t)v * HID;
    const float* w = Wih0 + (size_t)row * (HID + NPROP);
    float s = 0.f, comp = 0.f;
    for (int q = 0; q < HID; q++) {
        float a = e[q], b = w[q];
        float p = a * b;
        float ep = fmaf(a, b, -p);
        float t = s + p;
        float z = t - s;
        float err = (s - (t - z)) + (p - z);
        s = t;
        comp += ep + err;
    }
    g_emb_table[v][r] = (double)s + (double)comp;
}

__global__ void prep_base0(const float* __restrict__ prop,
                           const float* __restrict__ Wih0) {
    int idx = blockIdx.x * blockDim.x + threadIdx.x;
    if (idx >= BATCH * NG) return;
    int b = idx / NG, r = idx % NG;
    int row = (r & 3) * HID + (r >> 2);
    double s = 0.0;
    const float* wr = Wih0 + (size_t)row * (HID + NPROP) + HID;
    for (int p = 0; p < NPROP; p++) s += (double)prop[b * NPROP + p] * (double)wr[p];
    g_base0[b][r] = s;
}

// ---------------- fused LSTM layer: bf16x3 mma GEMM, cp.async pipelined ----------------
// CTA 128gr x 64b, 8 warps (4 gr x 2 b), warp tile 32x32.
// K pipelined in chunks of 32 halves (2 kt) with cp.async double buffering.
template <bool L0>
__global__ __launch_bounds__(256, 1)
void lstm_mma_kernel(int layer, int par) {
    __shared__ __align__(16) union SmemT {
        __nv_bfloat16 x[2][3][64][40];   // [buf][split][b][k(32)+pad8]
        float sp[128][66];
    } sm;

    const int tid = threadIdx.x;
    const int wid = tid >> 5;
    const int T   = tid & 31;
    const int mw  = wid & 3;
    const int nw  = wid >> 2;
    const int grbase = blockIdx.x * 128;
    const int bbase  = blockIdx.y * 64;
    const int tq = T >> 2;
    const int tr = T & 3;
    const int mt0 = blockIdx.x * 8 + mw * 2;
    const int frow = tid >> 2;      // fill row 0..63
    const int fj   = tid & 3;       // fill 16B quad 0..3

    float acc[2][4][4], rih[2][4][4];
#pragma unroll
    for (int mi = 0; mi < 2; mi++)
#pragma unroll
        for (int ni = 0; ni < 4; ni++)
#pragma unroll
            for (int q = 0; q < 4; q++) acc[mi][ni][q] = 0.f;

    unsigned sbase = (unsigned)__cvta_generic_to_shared(&sm.x[0][0][0][0]);
    unsigned wb[2][2][3][4];

    const int nhalf = L0 ? 1 : 2;
    for (int half = 0; half < nhalf; half++) {
        const __nv_bfloat16* Xp[3];
        const uint4* Wb[2];
#pragma unroll
        for (int s = 0; s < 3; s++) {
            if (L0)            Xp[s] = &g_xs[s][0][par][0][0];
            else if (half == 0) Xp[s] = &g_xs[s][layer - 1][par ^ 1][0][0];
            else                Xp[s] = &g_xs[s][layer][par][0][0];
        }
#pragma unroll
        for (int mi = 0; mi < 2; mi++) {
            if (L0) Wb[mi] = (const uint4*)&g_w0[mt0 + mi][0][0][0][0];
            else    Wb[mi] = (const uint4*)&g_w12[layer - 1][mt0 + mi][half * 64][0][0][0];
        }

        // prime: fill chunk 0 -> buf0, chunk 1 -> buf1
#pragma unroll
        for (int pb = 0; pb < 2; pb++) {
#pragma unroll
            for (int s = 0; s < 3; s++) {
                const __nv_bfloat16* src = Xp[s] + (size_t)(bbase + frow) * HID + pb * 32 + fj * 8;
                unsigned dst = sbase + (unsigned)((((pb * 3 + s) * 64 + frow) * 40 + fj * 8) * 2);
                asm volatile("cp.async.ca.shared.global [%0],[%1],16;\n" :: "r"(dst), "l"(src));
            }
            asm volatile("cp.async.commit_group;\n");
        }
        // prime weight regs for kt 0 into wb[0]
#pragma unroll
        for (int mi = 0; mi < 2; mi++)
#pragma unroll
            for (int s = 0; s < 3; s++) {
                uint4 v = Wb[mi][s * 32 + T];
                wb[0][mi][s][0] = v.x; wb[0][mi][s][1] = v.y;
                wb[0][mi][s][2] = v.z; wb[0][mi][s][3] = v.w;
            }

        for (int ch = 0; ch < 32; ch++) {
            asm volatile("cp.async.wait_group 1;\n");
            __syncthreads();
            const int buf = ch & 1;
#pragma unroll
            for (int kti = 0; kti < 2; kti++) {
                const int cur = kti;        // wb parity holding current kt
                const int nxt = kti ^ 1;
                int ktn = 2 * ch + kti + 1;
                if (ktn > 63) ktn = 63;
                // prefetch next kt weights
#pragma unroll
                for (int mi = 0; mi < 2; mi++)
#pragma unroll
                    for (int s = 0; s < 3; s++) {
                        uint4 v = Wb[mi][(ktn * 3 + s) * 32 + T];
                        wb[nxt][mi][s][0] = v.x; wb[nxt][mi][s][1] = v.y;
                        wb[nxt][mi][s][2] = v.z; wb[nxt][mi][s][3] = v.w;
                    }
                // activation fragments from smem (conflict-free: stride 20 words)
                unsigned bf[3][4][2];
#pragma unroll
                for (int s = 0; s < 3; s++)
#pragma unroll
                    for (int ni = 0; ni < 4; ni++) {
                        int n = nw * 32 + ni * 8 + tq;
                        const __nv_bfloat16* p = &sm.x[buf][s][n][kti * 16 + 2 * tr];
                        bf[s][ni][0] = *(const unsigned*)p;
                        bf[s][ni][1] = *(const unsigned*)(p + 8);
                    }
                // 6 mmas per (mi,ni), small terms first
#pragma unroll
                for (int mi = 0; mi < 2; mi++)
#pragma unroll
                    for (int ni = 0; ni < 4; ni++) {
                        float* d = acc[mi][ni];
                        mma_bf16(d, wb[cur][mi][2], bf[0][ni]);  // wl*xh
                        mma_bf16(d, wb[cur][mi][0], bf[2][ni]);  // wh*xl
                        mma_bf16(d, wb[cur][mi][1], bf[1][ni]);  // wm*xm
                        mma_bf16(d, wb[cur][mi][1], bf[0][ni]);  // wm*xh
                        mma_bf16(d, wb[cur][mi][0], bf[1][ni]);  // wh*xm
                        mma_bf16(d, wb[cur][mi][0], bf[0][ni]);  // wh*xh
                    }
            }
            __syncthreads();
            if (ch + 2 < 32) {
                int kc = (ch + 2) * 32;
#pragma unroll
                for (int s = 0; s < 3; s++) {
                    const __nv_bfloat16* src = Xp[s] + (size_t)(bbase + frow) * HID + kc + fj * 8;
                    unsigned dst = sbase + (unsigned)((((buf * 3 + s) * 64 + frow) * 40 + fj * 8) * 2);
                    asm volatile("cp.async.ca.shared.global [%0],[%1],16;\n" :: "r"(dst), "l"(src));
                }
            }
            asm volatile("cp.async.commit_group;\n");
        }

        if (!L0 && half == 0) {
            // snapshot ih-GEMM (rounded-at-fp32 by construction), reset accumulator
#pragma unroll
            for (int mi = 0; mi < 2; mi++)
#pragma unroll
                for (int ni = 0; ni < 4; ni++)
#pragma unroll
                    for (int q = 0; q < 4; q++) {
                        rih[mi][ni][q] = acc[mi][ni][q];
                        acc[mi][ni][q] = 0.f;
                    }
        }
    }

    asm volatile("cp.async.wait_group 0;\n");
    __syncthreads();

    // stage gates to smem (regroup i,f,g,o per unit), add biases for layers 1,2
#pragma unroll
    for (int mi = 0; mi < 2; mi++) {
        int r0 = mw * 32 + mi * 16 + tq;
        float bi0 = 0.f, bh0 = 0.f, bi8 = 0.f, bh8 = 0.f;
        if (!L0) {
            bi0 = g_bih[layer][grbase + r0];      bh0 = g_bhh[layer][grbase + r0];
            bi8 = g_bih[layer][grbase + r0 + 8];  bh8 = g_bhh[layer][grbase + r0 + 8];
        }
#pragma unroll
        for (int ni = 0; ni < 4; ni++) {
            int c0 = nw * 32 + ni * 8 + 2 * tr;
            float d0 = acc[mi][ni][0];
            float d1 = acc[mi][ni][1];
            float d2 = acc[mi][ni][2];
            float d3 = acc[mi][ni][3];
            if (!L0) {
                d0 = ((rih[mi][ni][0] + d0) + bi0) + bh0;
                d1 = ((rih[mi][ni][1] + d1) + bi0) + bh0;
                d2 = ((rih[mi][ni][2] + d2) + bi8) + bh8;
                d3 = ((rih[mi][ni][3] + d3) + bi8) + bh8;
            }
            *(float2*)&sm.sp[r0][c0]     = make_float2(d0, d1);
            *(float2*)&sm.sp[r0 + 8][c0] = make_float2(d2, d3);
        }
    }
    __syncthreads();

    // LSTM epilogue: 32 units x 64 batch per CTA
    const int un = tid & 31;
    const int bq = tid >> 5;
    const int j  = (grbase >> 2) + un;
    float* C    = &g_c[layer][0][0];
    float* Hout = &g_h[layer][par ^ 1][0][0];
    const int gr0 = grbase + un * 4;
#pragma unroll
    for (int r = 0; r < 8; r++) {
        int bl = bq * 8 + r;
        int b  = bbase + bl;
        float p0 = sm.sp[un * 4 + 0][bl];
        float p1 = sm.sp[un * 4 + 1][bl];
        float p2 = sm.sp[un * 4 + 2][bl];
        float p3 = sm.sp[un * 4 + 3][bl];
        if (L0) {
            int tk = g_tok[b];
            float v0 = (float)(g_emb_table[tk][gr0 + 0] + g_base0[b][gr0 + 0]);
            float v1 = (float)(g_emb_table[tk][gr0 + 1] + g_base0[b][gr0 + 1]);
            float v2 = (float)(g_emb_table[tk][gr0 + 2] + g_base0[b][gr0 + 2]);
            float v3 = (float)(g_emb_table[tk][gr0 + 3] + g_base0[b][gr0 + 3]);
            p0 = ((v0 + p0) + g_bih[0][gr0 + 0]) + g_bhh[0][gr0 + 0];
            p1 = ((v1 + p1) + g_bih[0][gr0 + 1]) + g_bhh[0][gr0 + 1];
            p2 = ((v2 + p2) + g_bih[0][gr0 + 2]) + g_bhh[0][gr0 + 2];
            p3 = ((v3 + p3) + g_bih[0][gr0 + 3]) + g_bhh[0][gr0 + 3];
        }
        float iv = xla_sigmoid(p0);
        float fv = xla_sigmoid(p1);
        float gv = xla_tanh(p2);
        float ov = xla_sigmoid(p3);
        float c = C[(size_t)b * HID + j];
        c = fmaf(fv, c, iv * gv);
        C[(size_t)b * HID + j] = c;
        float h = ov * xla_tanh(c);
        Hout[(size_t)b * HID + j] = h;
        // exact bf16 split-3 of h
        __nv_bfloat16 hh = __float2bfloat16(h);
        float r1 = h - __bfloat162float(hh);
        __nv_bfloat16 hm = __float2bfloat16(r1);
        float r2 = r1 - __bfloat162float(hm);
        g_xs[0][layer][par ^ 1][b][j] = hh;
        g_xs[1][layer][par ^ 1][b][j] = hm;
        g_xs[2][layer][par ^ 1][b][j] = __float2bfloat16(r2);
    }
}

// ---------------- decode: fp32 logits, output write, greedy argmax ----------------
__global__ void decode_kernel(const float* __restrict__ Wdec,
                              const float* __restrict__ bdec,
                              float* __restrict__ out, int t, int par) {
    __shared__ float slog[NOUT];
    int b = blockIdx.x;
    int tid = threadIdx.x;
    int w = tid >> 5, lane = tid & 31;
    const float* h2 = &g_h[2][par ^ 1][b][0];
    for (int o = w; o < NOUT; o += 8) {
        const float* wr = Wdec + (size_t)o * HID;
        float s = 0.f;
        for (int k = lane; k < HID; k += 32) s = fmaf(h2[k], wr[k], s);
#pragma unroll
        for (int off = 16; off; off >>= 1) s += __shfl_down_sync(0xffffffffu, s, off);
        if (lane == 0) {
            float sf = s + bdec[o];
            slog[o] = sf;
            out[((size_t)b * SEQT + t) * NOUT + o] = sf;
        }
    }
    __syncthreads();
    if (tid == 0) {
        int best = 0;
        float bv = slog[0];
        for (int o = 1; o < NOUT; o++)
            if (slog[o] > bv) { bv = slog[o]; best = o; }  // first-max tie rule
        g_tok[b] = best;
    }
}

// ---------------- finalize ----------------
__global__ void finalize_kernel(float* __restrict__ out) {
    const int HB = NLAYER * BATCH * HID;
    const size_t base = (size_t)BATCH * SEQT * NOUT;
    for (int i = blockIdx.x * blockDim.x + threadIdx.x; i < 2 * HB;
         i += gridDim.x * blockDim.x) {
        if (i < HB) {
            int l = i / (BATCH * HID);
            int r = i % (BATCH * HID);
            out[base + i] = ((float*)g_h)[((size_t)l * 2 + 0) * BATCH * HID + r];
        } else {
            out[base + i] = ((float*)g_c)[i - HB];
        }
    }
}

// ---------------- launcher ----------------
extern "C" void kernel_launch(void* const* d_in, const int* in_sizes, int n_in,
                              void* d_out, int out_size) {
    (void)in_sizes; (void)n_in; (void)out_size;
    // Inputs: x, properties, emb, W_dec, b_dec, W_ih0, W_ih_rest, W_hh, b_ih, b_hh
    const float* properties = (const float*)d_in[1];
    const float* emb        = (const float*)d_in[2];
    const float* W_dec      = (const float*)d_in[3];
    const float* b_dec      = (const float*)d_in[4];
    const float* W_ih0      = (const float*)d_in[5];
    const float* W_ih_rest  = (const float*)d_in[6];
    const float* W_hh       = (const float*)d_in[7];
    const float* b_ih       = (const float*)d_in[8];
    const float* b_hh       = (const float*)d_in[9];
    float* out = (float*)d_out;

    prep_state<<<1024, 256>>>();
    prep_bias<<<(NLAYER * NG + 255) / 256, 256>>>(b_ih, b_hh);
    prep_w12<<<(2 * 256 * 128 * 32 * 4 + 255) / 256, 256>>>(W_ih_rest, W_hh);
    prep_w0<<<(256 * 64 * 32 * 4 + 255) / 256, 256>>>(W_hh);
    prep_emb_table<<<(NVOCAB * NG + 255) / 256, 256>>>(emb, W_ih0);
    prep_base0<<<(BATCH * NG + 255) / 256, 256>>>(properties, W_ih0);

    dim3 grid(NG / 128, BATCH / 64);   // 32 x 4 = 128 CTAs
    for (int t = 0; t < SEQT; t++) {
        int par = t & 1;
        lstm_mma_kernel<true><<<grid, 256>>>(0, par);
        lstm_mma_kernel<false><<<grid, 256>>>(1, par);
        lstm_mma_kernel<false><<<grid, 256>>>(2, par);
        decode_kernel<<<BATCH, 256>>>(W_dec, b_dec, out, t, par);
    }
    finalize_kernel<<<1536, 256>>>(out);
}

// round 8
// speedup vs baseline: 1.9510x; 1.0029x over previous
#include <cuda_runtime.h>
#include <cuda_bf16.h>
#include <math.h>

// Problem constants
#define HID    1024
#define BATCH  256
#define NLAYER 3
#define NPROP  4
#define SEQT   128
#define NOUT   47
#define NVOCAB 47
#define NG     4096   // 4*HID

// ---------------- device scratch (static, allocation-free) ----------------
// Weight fragments, bf16 exact split-3 (hi, mid, lo), mma m16n8k16 A-layout,
// gate-reordered gr = 4j+g. Per [mt][kt]: 3 split planes x 32 lanes x uint4.
__device__ unsigned g_w12[2][256][128][3][32][4];  // layers 1,2 [Wih|Whh]: 100.7 MB
__device__ unsigned g_w0 [256][64][3][32][4];      // layer 0 Whh: 25.2 MB
__device__ float  g_bih[NLAYER][NG];
__device__ float  g_bhh[NLAYER][NG];
__device__ double g_emb_table[NVOCAB][NG];         // W_ih0[:,:H] @ emb[v] (exact)
__device__ double g_base0[BATCH][NG];              // W_ih0[:,H:] @ prop[b] (exact)
__device__ float  g_h[NLAYER][2][BATCH][HID];      // double-buffered hidden (fp32)
__device__ __nv_bfloat16 g_xs[3][NLAYER][2][BATCH][HID];  // bf16 split planes of h
__device__ float  g_c[NLAYER][BATCH][HID];
__device__ int    g_tok[BATCH];

// ---------------- XLA-matched transcendentals ----------------
__device__ __forceinline__ float xla_tanh(float x) {
    float ax = fabsf(x);
    float xc = fminf(fmaxf(x, -7.90531110763549805f), 7.90531110763549805f);
    float x2 = xc * xc;
    float np = -2.76076847742355e-16f;
    np = fmaf(x2, np, 2.00018790482477e-13f);
    np = fmaf(x2, np, -8.60467152213735e-11f);
    np = fmaf(x2, np, 5.12229709037114e-08f);
    np = fmaf(x2, np, 1.48572235717979e-05f);
    np = fmaf(x2, np, 6.37261928875436e-04f);
    np = fmaf(x2, np, 4.89352455891786e-03f);
    float num = xc * np;
    float dp = 1.19825839466702e-06f;
    dp = fmaf(x2, dp, 1.18534705686654e-04f);
    dp = fmaf(x2, dp, 2.26843463243900e-03f);
    dp = fmaf(x2, dp, 4.89352518554385e-03f);
    float r = __fdiv_rn(num, dp);
    return (ax < 0.0004f) ? x : r;
}
__device__ __forceinline__ float xla_sigmoid(float x) {
    return fmaf(0.5f, xla_tanh(0.5f * x), 0.5f);
}

// ---------------- mma.sync bf16 wrapper ----------------
__device__ __forceinline__ void mma_bf16(float* d, const unsigned* a, const unsigned* b) {
    asm volatile(
        "mma.sync.aligned.m16n8k16.row.col.f32.bf16.bf16.f32 "
        "{%0,%1,%2,%3}, {%4,%5,%6,%7}, {%8,%9}, {%0,%1,%2,%3};\n"
        : "+f"(d[0]), "+f"(d[1]), "+f"(d[2]), "+f"(d[3])
        : "r"(a[0]), "r"(a[1]), "r"(a[2]), "r"(a[3]), "r"(b[0]), "r"(b[1]));
}

// Exact bf16 split-3 of an fp32 pair, packed (low half = first element)
__device__ __forceinline__ void split3_pack(float v0, float v1,
                                            unsigned& ph, unsigned& pm, unsigned& pl) {
    __nv_bfloat16 h0 = __float2bfloat16(v0), h1 = __float2bfloat16(v1);
    float r0 = v0 - __bfloat162float(h0), r1 = v1 - __bfloat162float(h1);
    __nv_bfloat16 m0 = __float2bfloat16(r0), m1 = __float2bfloat16(r1);
    float s0 = r0 - __bfloat162float(m0), s1 = r1 - __bfloat162float(m1);
    __nv_bfloat16 l0 = __float2bfloat16(s0), l1 = __float2bfloat16(s1);
    __nv_bfloat162 H = __halves2bfloat162(h0, h1);
    __nv_bfloat162 M = __halves2bfloat162(m0, m1);
    __nv_bfloat162 L = __halves2bfloat162(l0, l1);
    ph = *(unsigned*)&H; pm = *(unsigned*)&M; pl = *(unsigned*)&L;
}

// ---------------- precompute kernels ----------------

__global__ void prep_state() {
    const int NH = NLAYER * 2 * BATCH * HID;
    const int NC = NLAYER * BATCH * HID;
    const int NXS = 3 * NLAYER * 2 * BATCH * HID / 2;   // g_xs as u32 words
    float* ph = (float*)g_h;
    float* pc = (float*)g_c;
    unsigned* pxs = (unsigned*)g_xs;
    int total = NH + NC + NXS + BATCH;
    for (int i = blockIdx.x * blockDim.x + threadIdx.x; i < total;
         i += gridDim.x * blockDim.x) {
        if (i < NH) ph[i] = 0.f;
        else if (i < NH + NC) pc[i - NH] = 0.f;
        else if (i < NH + NC + NXS) pxs[i - NH - NC] = 0u;
        else g_tok[i - NH - NC - NXS] = 0;
    }
}

__global__ void prep_bias(const float* __restrict__ bih, const float* __restrict__ bhh) {
    int i = blockIdx.x * blockDim.x + threadIdx.x;
    if (i >= NLAYER * NG) return;
    int l = i / NG, r = i % NG;
    int row = (r & 3) * HID + (r >> 2);
    g_bih[l][r] = bih[l * NG + row];
    g_bhh[l][r] = bhh[l * NG + row];
}

// weights layers 1,2: [W_ih | W_hh] -> bf16x3 fragment planes
__global__ void prep_w12(const float* __restrict__ Wih_rest,  // [2][NG][HID]
                         const float* __restrict__ Whh) {     // [3][NG][HID]
    int idx = blockIdx.x * blockDim.x + threadIdx.x;
    if (idx >= 2 * 256 * 128 * 32 * 4) return;
    int r  = idx & 3;
    int T  = (idx >> 2) & 31;
    int kt = (idx >> 7) & 127;
    int mt = (idx >> 14) & 255;
    int lm = idx >> 22;
    int gr = mt * 16 + (T >> 2) + 8 * (r & 1);
    int k  = kt * 16 + 2 * (T & 3) + 8 * (r >> 1);
    int row = (gr & 3) * HID + (gr >> 2);
    float v0, v1;
    if (k < HID) {
        const float* s = Wih_rest + ((size_t)lm * NG + row) * HID + k;
        v0 = s[0]; v1 = s[1];
    } else {
        const float* s = Whh + ((size_t)(lm + 1) * NG + row) * HID + (k - HID);
        v0 = s[0]; v1 = s[1];
    }
    unsigned ph, pm, pl;
    split3_pack(v0, v1, ph, pm, pl);
    g_w12[lm][mt][kt][0][T][r] = ph;
    g_w12[lm][mt][kt][1][T][r] = pm;
    g_w12[lm][mt][kt][2][T][r] = pl;
}

// layer 0 W_hh fragments
__global__ void prep_w0(const float* __restrict__ Whh) {
    int idx = blockIdx.x * blockDim.x + threadIdx.x;
    if (idx >= 256 * 64 * 32 * 4) return;
    int r  = idx & 3;
    int T  = (idx >> 2) & 31;
    int kt = (idx >> 7) & 63;
    int mt = idx >> 13;
    int gr = mt * 16 + (T >> 2) + 8 * (r & 1);
    int k  = kt * 16 + 2 * (T & 3) + 8 * (r >> 1);
    int row = (gr & 3) * HID + (gr >> 2);
    const float* s = Whh + (size_t)row * HID + k;
    unsigned ph, pm, pl;
    split3_pack(s[0], s[1], ph, pm, pl);
    g_w0[mt][kt][0][T][r] = ph;
    g_w0[mt][kt][1][T][r] = pm;
    g_w0[mt][kt][2][T][r] = pl;
}

// emb_table: exact fp32 dot via FMA two-product + two-sum
__global__ void prep_emb_table(const float* __restrict__ emb,
                               const float* __restrict__ Wih0) {
    int idx = blockIdx.x * blockDim.x + threadIdx.x;
    if (idx >= NVOCAB * NG) return;
    int v = idx / NG, r = idx % NG;
    int row = (r & 3) * HID + (r >> 2);
    const float* e = emb + (size_t)v * HID;
    const float* w = Wih0 + (size_t)row * (HID + NPROP);
    float s = 0.f, comp = 0.f;
    for (int q = 0; q < HID; q++) {
        float a = e[q], b = w[q];
        float p = a * b;
        float ep = fmaf(a, b, -p);
        float t = s + p;
        float z = t - s;
        float err = (s - (t - z)) + (p - z);
        s = t;
        comp += ep + err;
    }
    g_emb_table[v][r] = (double)s + (double)comp;
}

__global__ void prep_base0(const float* __restrict__ prop,
                           const float* __restrict__ Wih0) {
    int idx = blockIdx.x * blockDim.x + threadIdx.x;
    if (idx >= BATCH * NG) return;
    int b = idx / NG, r = idx % NG;
    int row = (r & 3) * HID + (r >> 2);
    double s = 0.0;
    const float* wr = Wih0 + (size_t)row * (HID + NPROP) + HID;
    for (int p = 0; p < NPROP; p++) s += (double)prop[b * NPROP + p] * (double)wr[p];
    g_base0[b][r] = s;
}

// ---------------- fused LSTM layer: bf16x3 mma GEMM, cp.async pipelined ----------------
// CTA 128gr x 64b, 8 warps (4 gr x 2 b), warp tile 32x32.
// K pipelined in chunks of 32 halves (2 kt) with cp.async double buffering.
template <bool L0>
__global__ __launch_bounds__(256, 1)
void lstm_mma_kernel(int layer, int par) {
    __shared__ __align__(16) union SmemT {
        __nv_bfloat16 x[2][3][64][40];   // [buf][split][b][k(32)+pad8]
        float sp[128][66];
    } sm;

    const int tid = threadIdx.x;
    const int wid = tid >> 5;
    const int T   = tid & 31;
    const int mw  = wid & 3;
    const int nw  = wid >> 2;
    const int grbase = blockIdx.x * 128;
    const int bbase  = blockIdx.y * 64;
    const int tq = T >> 2;
    const int tr = T & 3;
    const int mt0 = blockIdx.x * 8 + mw * 2;
    const int frow = tid >> 2;      // fill row 0..63
    const int fj   = tid & 3;       // fill 16B quad 0..3

    float acc[2][4][4], rih[2][4][4];
#pragma unroll
    for (int mi = 0; mi < 2; mi++)
#pragma unroll
        for (int ni = 0; ni < 4; ni++)
#pragma unroll
            for (int q = 0; q < 4; q++) acc[mi][ni][q] = 0.f;

    unsigned sbase = (unsigned)__cvta_generic_to_shared(&sm.x[0][0][0][0]);
    unsigned wb[2][2][3][4];

    const int nhalf = L0 ? 1 : 2;
    for (int half = 0; half < nhalf; half++) {
        const __nv_bfloat16* Xp[3];
        const uint4* Wb[2];
#pragma unroll
        for (int s = 0; s < 3; s++) {
            if (L0)            Xp[s] = &g_xs[s][0][par][0][0];
            else if (half == 0) Xp[s] = &g_xs[s][layer - 1][par ^ 1][0][0];
            else                Xp[s] = &g_xs[s][layer][par][0][0];
        }
#pragma unroll
        for (int mi = 0; mi < 2; mi++) {
            if (L0) Wb[mi] = (const uint4*)&g_w0[mt0 + mi][0][0][0][0];
            else    Wb[mi] = (const uint4*)&g_w12[layer - 1][mt0 + mi][half * 64][0][0][0];
        }

        // prime: fill chunk 0 -> buf0, chunk 1 -> buf1
#pragma unroll
        for (int pb = 0; pb < 2; pb++) {
#pragma unroll
            for (int s = 0; s < 3; s++) {
                const __nv_bfloat16* src = Xp[s] + (size_t)(bbase + frow) * HID + pb * 32 + fj * 8;
                unsigned dst = sbase + (unsigned)((((pb * 3 + s) * 64 + frow) * 40 + fj * 8) * 2);
                asm volatile("cp.async.ca.shared.global [%0],[%1],16;\n" :: "r"(dst), "l"(src));
            }
            asm volatile("cp.async.commit_group;\n");
        }
        // prime weight regs for kt 0 into wb[0]
#pragma unroll
        for (int mi = 0; mi < 2; mi++)
#pragma unroll
            for (int s = 0; s < 3; s++) {
                uint4 v = Wb[mi][s * 32 + T];
                wb[0][mi][s][0] = v.x; wb[0][mi][s][1] = v.y;
                wb[0][mi][s][2] = v.z; wb[0][mi][s][3] = v.w;
            }

        for (int ch = 0; ch < 32; ch++) {
            asm volatile("cp.async.wait_group 1;\n");
            __syncthreads();
            const int buf = ch & 1;
#pragma unroll
            for (int kti = 0; kti < 2; kti++) {
                const int cur = kti;        // wb parity holding current kt
                const int nxt = kti ^ 1;
                int ktn = 2 * ch + kti + 1;
                if (ktn > 63) ktn = 63;
                // prefetch next kt weights
#pragma unroll
                for (int mi = 0; mi < 2; mi++)
#pragma unroll
                    for (int s = 0; s < 3; s++) {
                        uint4 v = Wb[mi][(ktn * 3 + s) * 32 + T];
                        wb[nxt][mi][s][0] = v.x; wb[nxt][mi][s][1] = v.y;
                        wb[nxt][mi][s][2] = v.z; wb[nxt][mi][s][3] = v.w;
                    }
                // activation fragments from smem (conflict-free: stride 20 words)
                unsigned bf[3][4][2];
#pragma unroll
                for (int s = 0; s < 3; s++)
#pragma unroll
                    for (int ni = 0; ni < 4; ni++) {
                        int n = nw * 32 + ni * 8 + tq;
                        const __nv_bfloat16* p = &sm.x[buf][s][n][kti * 16 + 2 * tr];
                        bf[s][ni][0] = *(const unsigned*)p;
                        bf[s][ni][1] = *(const unsigned*)(p + 8);
                    }
                // 6 mmas per (mi,ni), small terms first
#pragma unroll
                for (int mi = 0; mi < 2; mi++)
#pragma unroll
                    for (int ni = 0; ni < 4; ni++) {
                        float* d = acc[mi][ni];
                        mma_bf16(d, wb[cur][mi][2], bf[0][ni]);  // wl*xh
                        mma_bf16(d, wb[cur][mi][0], bf[2][ni]);  // wh*xl
                        mma_bf16(d, wb[cur][mi][1], bf[1][ni]);  // wm*xm
                        mma_bf16(d, wb[cur][mi][1], bf[0][ni]);  // wm*xh
                        mma_bf16(d, wb[cur][mi][0], bf[1][ni]);  // wh*xm
                        mma_bf16(d, wb[cur][mi][0], bf[0][ni]);  // wh*xh
                    }
            }
            __syncthreads();
            if (ch + 2 < 32) {
                int kc = (ch + 2) * 32;
#pragma unroll
                for (int s = 0; s < 3; s++) {
                    const __nv_bfloat16* src = Xp[s] + (size_t)(bbase + frow) * HID + kc + fj * 8;
                    unsigned dst = sbase + (unsigned)((((buf * 3 + s) * 64 + frow) * 40 + fj * 8) * 2);
                    asm volatile("cp.async.ca.shared.global [%0],[%1],16;\n" :: "r"(dst), "l"(src));
                }
            }
            asm volatile("cp.async.commit_group;\n");
        }

        if (!L0 && half == 0) {
            // snapshot ih-GEMM (rounded-at-fp32 by construction), reset accumulator
#pragma unroll
            for (int mi = 0; mi < 2; mi++)
#pragma unroll
                for (int ni = 0; ni < 4; ni++)
#pragma unroll
                    for (int q = 0; q < 4; q++) {
                        rih[mi][ni][q] = acc[mi][ni][q];
                        acc[mi][ni][q] = 0.f;
                    }
        }
    }

    asm volatile("cp.async.wait_group 0;\n");
    __syncthreads();

    // stage gates to smem (regroup i,f,g,o per unit), add biases for layers 1,2
#pragma unroll
    for (int mi = 0; mi < 2; mi++) {
        int r0 = mw * 32 + mi * 16 + tq;
        float bi0 = 0.f, bh0 = 0.f, bi8 = 0.f, bh8 = 0.f;
        if (!L0) {
            bi0 = g_bih[layer][grbase + r0];      bh0 = g_bhh[layer][grbase + r0];
            bi8 = g_bih[layer][grbase + r0 + 8];  bh8 = g_bhh[layer][grbase + r0 + 8];
        }
#pragma unroll
        for (int ni = 0; ni < 4; ni++) {
            int c0 = nw * 32 + ni * 8 + 2 * tr;
            float d0 = acc[mi][ni][0];
            float d1 = acc[mi][ni][1];
            float d2 = acc[mi][ni][2];
            float d3 = acc[mi][ni][3];
            if (!L0) {
                d0 = ((rih[mi][ni][0] + d0) + bi0) + bh0;
                d1 = ((rih[mi][ni][1] + d1) + bi0) + bh0;
                d2 = ((rih[mi][ni][2] + d2) + bi8) + bh8;
                d3 = ((rih[mi][ni][3] + d3) + bi8) + bh8;
            }
            *(float2*)&sm.sp[r0][c0]     = make_float2(d0, d1);
            *(float2*)&sm.sp[r0 + 8][c0] = make_float2(d2, d3);
        }
    }
    __syncthreads();

    // LSTM epilogue: 32 units x 64 batch per CTA
    const int un = tid & 31;
    const int bq = tid >> 5;
    const int j  = (grbase >> 2) + un;
    float* C    = &g_c[layer][0][0];
    float* Hout = &g_h[layer][par ^ 1][0][0];
    const int gr0 = grbase + un * 4;
#pragma unroll
    for (int r = 0; r < 8; r++) {
        int bl = bq * 8 + r;
        int b  = bbase + bl;
        float p0 = sm.sp[un * 4 + 0][bl];
        float p1 = sm.sp[un * 4 + 1][bl];
        float p2 = sm.sp[un * 4 + 2][bl];
        float p3 = sm.sp[un * 4 + 3][bl];
        if (L0) {
            int tk = g_tok[b];
            float v0 = (float)(g_emb_table[tk][gr0 + 0] + g_base0[b][gr0 + 0]);
            float v1 = (float)(g_emb_table[tk][gr0 + 1] + g_base0[b][gr0 + 1]);
            float v2 = (float)(g_emb_table[tk][gr0 + 2] + g_base0[b][gr0 + 2]);
            float v3 = (float)(g_emb_table[tk][gr0 + 3] + g_base0[b][gr0 + 3]);
            p0 = ((v0 + p0) + g_bih[0][gr0 + 0]) + g_bhh[0][gr0 + 0];
            p1 = ((v1 + p1) + g_bih[0][gr0 + 1]) + g_bhh[0][gr0 + 1];
            p2 = ((v2 + p2) + g_bih[0][gr0 + 2]) + g_bhh[0][gr0 + 2];
            p3 = ((v3 + p3) + g_bih[0][gr0 + 3]) + g_bhh[0][gr0 + 3];
        }
        float iv = xla_sigmoid(p0);
        float fv = xla_sigmoid(p1);
        float gv = xla_tanh(p2);
        float ov = xla_sigmoid(p3);
        float c = C[(size_t)b * HID + j];
        c = fmaf(fv, c, iv * gv);
        C[(size_t)b * HID + j] = c;
        float h = ov * xla_tanh(c);
        Hout[(size_t)b * HID + j] = h;
        // exact bf16 split-3 of h
        __nv_bfloat16 hh = __float2bfloat16(h);
        float r1 = h - __bfloat162float(hh);
        __nv_bfloat16 hm = __float2bfloat16(r1);
        float r2 = r1 - __bfloat162float(hm);
        g_xs[0][layer][par ^ 1][b][j] = hh;
        g_xs[1][layer][par ^ 1][b][j] = hm;
        g_xs[2][layer][par ^ 1][b][j] = __float2bfloat16(r2);
    }
}

// ---------------- decode: fp32 logits, output write, greedy argmax ----------------
__global__ void decode_kernel(const float* __restrict__ Wdec,
                              const float* __restrict__ bdec,
                              float* __restrict__ out, int t, int par) {
    __shared__ float slog[NOUT];
    int b = blockIdx.x;
    int tid = threadIdx.x;
    int w = tid >> 5, lane = tid & 31;
    const float* h2 = &g_h[2][par ^ 1][b][0];
    for (int o = w; o < NOUT; o += 8) {
        const float* wr = Wdec + (size_t)o * HID;
        float s = 0.f;
        for (int k = lane; k < HID; k += 32) s = fmaf(h2[k], wr[k], s);
#pragma unroll
        for (int off = 16; off; off >>= 1) s += __shfl_down_sync(0xffffffffu, s, off);
        if (lane == 0) {
            float sf = s + bdec[o];
            slog[o] = sf;
            out[((size_t)b * SEQT + t) * NOUT + o] = sf;
        }
    }
    __syncthreads();
    if (tid == 0) {
        int best = 0;
        float bv = slog[0];
        for (int o = 1; o < NOUT; o++)
            if (slog[o] > bv) { bv = slog[o]; best = o; }  // first-max tie rule
        g_tok[b] = best;
    }
}

// ---------------- finalize ----------------
__global__ void finalize_kernel(float* __restrict__ out) {
    const int HB = NLAYER * BATCH * HID;
    const size_t base = (size_t)BATCH * SEQT * NOUT;
    for (int i = blockIdx.x * blockDim.x + threadIdx.x; i < 2 * HB;
         i += gridDim.x * blockDim.x) {
        if (i < HB) {
            int l = i / (BATCH * HID);
            int r = i % (BATCH * HID);
            out[base + i] = ((float*)g_h)[((size_t)l * 2 + 0) * BATCH * HID + r];
        } else {
            out[base + i] = ((float*)g_c)[i - HB];
        }
    }
}

// ---------------- launcher ----------------
extern "C" void kernel_launch(void* const* d_in, const int* in_sizes, int n_in,
                              void* d_out, int out_size) {
    (void)in_sizes; (void)n_in; (void)out_size;
    // Inputs: x, properties, emb, W_dec, b_dec, W_ih0, W_ih_rest, W_hh, b_ih, b_hh
    const float* properties = (const float*)d_in[1];
    const float* emb        = (const float*)d_in[2];
    const float* W_dec      = (const float*)d_in[3];
    const float* b_dec      = (const float*)d_in[4];
    const float* W_ih0      = (const float*)d_in[5];
    const float* W_ih_rest  = (const float*)d_in[6];
    const float* W_hh       = (const float*)d_in[7];
    const float* b_ih       = (const float*)d_in[8];
    const float* b_hh       = (const float*)d_in[9];
    float* out = (float*)d_out;

    prep_state<<<1024, 256>>>();
    prep_bias<<<(NLAYER * NG + 255) / 256, 256>>>(b_ih, b_hh);
    prep_w12<<<(2 * 256 * 128 * 32 * 4 + 255) / 256, 256>>>(W_ih_rest, W_hh);
    prep_w0<<<(256 * 64 * 32 * 4 + 255) / 256, 256>>>(W_hh);
    prep_emb_table<<<(NVOCAB * NG + 255) / 256, 256>>>(emb, W_ih0);
    prep_base0<<<(BATCH * NG + 255) / 256, 256>>>(properties, W_ih0);

    dim3 grid(NG / 128, BATCH / 64);   // 32 x 4 = 128 CTAs
    for (int t = 0; t < SEQT; t++) {
        int par = t & 1;
        lstm_mma_kernel<true><<<grid, 256>>>(0, par);
        lstm_mma_kernel<false><<<grid, 256>>>(1, par);
        lstm_mma_kernel<false><<<grid, 256>>>(2, par);
        decode_kernel<<<BATCH, 256>>>(W_dec, b_dec, out, t, par);
    }
    finalize_kernel<<<1536, 256>>>(out);
}